// round 1
// baseline (speedup 1.0000x reference)
#include <cuda_runtime.h>

#define NN 13
#define HD 128
#define NLAYER 8
#define NJ 17
#define DMAX 33
#define OBSD 348
#define SPC 8                 // samples per CTA
#define MREAL (SPC*NN)        // 104 real rows
#define MROWS 128             // padded M tile
#define XST 258               // xs row stride (floats), padded
#define NTHREADS 512
#define KTOT 256
#define KC 32

// Feature gather indices (from _build_feature_indices), -1 = padded zero
__constant__ int c_feat[NN][DMAX] = {
  {0,1,2,3,4,22,23,24,25,26,27,45,46,47,48,49,50,51,52,53,54,175,176,177,178,179,180,270,271,272,273,274,275},
  {5,6,28,29,55,56,57,58,59,60,61,62,63,64,181,182,183,184,185,186,276,277,278,279,280,281,-1,-1,-1,-1,-1,-1,-1},
  {7,30,65,66,67,68,69,70,71,72,73,74,187,188,189,190,191,192,253,254,255,282,283,284,285,286,287,-1,-1,-1,-1,-1,-1},
  {8,9,10,11,31,32,33,34,75,76,77,78,79,80,81,82,83,84,193,194,195,196,197,198,256,257,258,288,289,290,291,292,293},
  {11,34,85,86,87,88,89,90,91,92,93,94,199,200,201,202,203,204,259,294,295,296,297,298,299,-1,-1,-1,-1,-1,-1,-1,-1},
  {95,96,97,98,99,100,101,102,103,104,205,206,207,208,209,210,300,301,302,303,304,305,-1,-1,-1,-1,-1,-1,-1,-1,-1,-1,-1},
  {12,13,14,15,35,36,37,38,105,106,107,108,109,110,111,112,113,114,211,212,213,214,215,216,260,261,262,306,307,308,309,310,311},
  {15,38,115,116,117,118,119,120,121,122,123,124,217,218,219,220,221,222,263,312,313,314,315,316,317,-1,-1,-1,-1,-1,-1,-1,-1},
  {125,126,127,128,129,130,131,132,133,134,223,224,225,226,227,228,318,319,320,321,322,323,-1,-1,-1,-1,-1,-1,-1,-1,-1,-1,-1},
  {16,17,18,39,40,41,135,136,137,138,139,140,141,142,143,144,229,230,231,232,233,234,264,265,324,325,326,327,328,329,-1,-1,-1},
  {18,41,145,146,147,148,149,150,151,152,153,154,235,236,237,238,239,240,266,330,331,332,333,334,335,-1,-1,-1,-1,-1,-1,-1,-1},
  {19,20,21,42,43,44,155,156,157,158,159,160,161,162,163,164,241,242,243,244,245,246,267,268,336,337,338,339,340,341,-1,-1,-1},
  {21,44,165,166,167,168,169,170,171,172,173,174,247,248,249,250,251,252,269,342,343,344,345,346,347,-1,-1,-1,-1,-1,-1,-1,-1}
};

// agg[n] = sum over neighbors (kinematic tree, both directions)
__constant__ int c_nbr[NN][3] = {
  {1,9,11},{0,2,0},{1,3,6},{2,4,0},{3,5,0},{4,0,0},{2,7,0},
  {6,8,0},{7,0,0},{0,10,0},{9,0,0},{0,12,0},{11,0,0}
};
__constant__ int c_deg[NN] = {3,2,3,2,2,1,2,2,1,2,1,2,1};

__constant__ int c_jm0[NJ] = {1,1,1,2,2,2,3,2,2,2,6,0,0,9,0,0,11};
__constant__ int c_jm1[NJ] = {2,2,2,3,3,3,4,6,6,6,7,9,9,10,11,11,12};

__device__ __forceinline__ float eluf(float x) {
    return x > 0.0f ? x : expm1f(x);
}
__device__ __forceinline__ unsigned long long pk2(float lo, float hi) {
    unsigned long long r;
    asm("mov.b64 %0, {%1, %2};" : "=l"(r) : "f"(lo), "f"(hi));
    return r;
}
__device__ __forceinline__ void upk2(unsigned long long v, float& lo, float& hi) {
    asm("mov.b64 {%0, %1}, %2;" : "=f"(lo), "=f"(hi) : "l"(v));
}
// Blackwell packed dual-FP32 FMA (FFMA2): 2x fp32 FMA throughput
__device__ __forceinline__ void fma2(unsigned long long& d, unsigned long long a, unsigned long long b) {
    asm("fma.rn.f32x2 %0, %1, %2, %0;" : "+l"(d) : "l"(a), "l"(b));
}

__global__ __launch_bounds__(NTHREADS, 1)
void gnn_kernel(const float* __restrict__ obs,
                const float* __restrict__ W1, const float* __restrict__ b1,
                const float* __restrict__ W2, const float* __restrict__ b2,
                const float* __restrict__ Wmsg, const float* __restrict__ bmsg,
                const float* __restrict__ Wout, const float* __restrict__ bout,
                float* __restrict__ out)
{
    extern __shared__ float sm[];
    float* xs = sm;                        // [MROWS][XST] : cols 0..127 = x, 128..255 = agg
    float* wb = sm + MROWS * XST;          // [KC][HD] weight chunk; doubles as obs buffer
    float* hb = wb + KC * HD;              // [SPC][HD] encoder hidden
    float* scratch = xs + MREAL * XST;     // 24*258 floats (pad rows) as encoder reduce scratch

    const int tid = threadIdx.x;
    const int blk = blockIdx.x;
    const int base_s = blk * SPC;

    // ======== load obs tile ========
    float* obsb = wb; // [SPC][OBSD], 2784 floats <= 4096
    for (int i = tid; i < SPC * OBSD; i += NTHREADS) {
        int s = i / OBSD, f = i - s * OBSD;
        obsb[s * OBSD + f] = obs[(size_t)(base_s + s) * OBSD + f];
    }
    __syncthreads();

    const int hcol = tid & (HD - 1);
    const int sg = tid >> 7;   // 0..3 : K-split group

    // ======== encoder: x0 = W2 @ elu(W1 @ gather(obs)) per node ========
    for (int n = 0; n < NN; ++n) {
        // layer-1 partials, d-range split over sg
        float acc[SPC];
        #pragma unroll
        for (int s = 0; s < SPC; ++s) acc[s] = 0.0f;
        for (int d = sg; d < DMAX; d += 4) {
            int fi = c_feat[n][d];
            if (fi >= 0) {
                float w = __ldg(&W1[(n * DMAX + d) * HD + hcol]);
                #pragma unroll
                for (int s = 0; s < SPC; ++s)
                    acc[s] += obsb[s * OBSD + fi] * w;
            }
        }
        #pragma unroll
        for (int s = 0; s < SPC; ++s)
            scratch[(sg * SPC + s) * HD + hcol] = acc[s];
        __syncthreads();
        {   // reduce partials + bias + elu -> hb
            int s0 = sg * 2, s1 = s0 + 1;
            float v0 = b1[n * HD + hcol], v1 = v0;
            #pragma unroll
            for (int g = 0; g < 4; ++g) {
                v0 += scratch[(g * SPC + s0) * HD + hcol];
                v1 += scratch[(g * SPC + s1) * HD + hcol];
            }
            hb[s0 * HD + hcol] = eluf(v0);
            hb[s1 * HD + hcol] = eluf(v1);
        }
        __syncthreads();
        // layer-2 partials, k-range split over sg
        float acc2[SPC];
        #pragma unroll
        for (int s = 0; s < SPC; ++s) acc2[s] = 0.0f;
        for (int kk = sg * 32; kk < sg * 32 + 32; ++kk) {
            float w = __ldg(&W2[(n * HD + kk) * HD + hcol]);
            #pragma unroll
            for (int s = 0; s < SPC; ++s)
                acc2[s] += hb[s * HD + kk] * w;
        }
        #pragma unroll
        for (int s = 0; s < SPC; ++s)
            scratch[(sg * SPC + s) * HD + hcol] = acc2[s];
        __syncthreads();
        {   // reduce + bias -> xs (no activation, matches reference)
            int s0 = sg * 2, s1 = s0 + 1;
            float v0 = b2[n * HD + hcol], v1 = v0;
            #pragma unroll
            for (int g = 0; g < 4; ++g) {
                v0 += scratch[(g * SPC + s0) * HD + hcol];
                v1 += scratch[(g * SPC + s1) * HD + hcol];
            }
            xs[(s0 * NN + n) * XST + hcol] = v0;
            xs[(s1 * NN + n) * XST + hcol] = v1;
        }
        __syncthreads();
    }

    // zero the pad rows (they are read by dummy GEMM threads, never written)
    for (int i = tid; i < (MROWS - MREAL) * XST; i += NTHREADS)
        xs[MREAL * XST + i] = 0.0f;

    const int tx = tid & 15;     // N block: cols [tx*8, tx*8+8)
    const int ty = tid >> 4;     // M block: rows [ty*4, ty*4+4)
    const int hbase = tx * 8;

    // ======== 8 message-passing layers ========
    for (int l = 0; l < NLAYER; ++l) {
        // aggregation: agg[s,n] = sum_{nb in N(n)} x[s,nb]
        for (int i = tid; i < MREAL * HD; i += NTHREADS) {
            int h = i & (HD - 1);
            int m = i >> 7;              // 0..103, m = s*13 + n
            int n = m % NN;
            int s13 = m - n;
            float sum = 0.0f;
            int dg = c_deg[n];
            #pragma unroll
            for (int e = 0; e < 3; ++e)
                if (e < dg) sum += xs[(s13 + c_nbr[n][e]) * XST + h];
            xs[m * XST + HD + h] = sum;
        }

        // init packed accumulators with bias
        unsigned long long acc[4][4];
        {
            const float* bm = bmsg + l * HD + hbase;
            #pragma unroll
            for (int j = 0; j < 4; ++j) {
                unsigned long long bp = pk2(bm[2 * j], bm[2 * j + 1]);
                #pragma unroll
                for (int i = 0; i < 4; ++i) acc[i][j] = bp;
            }
        }

        const float* Wl = Wmsg + (size_t)l * KTOT * HD;
        for (int kc = 0; kc < KTOT / KC; ++kc) {
            __syncthreads();   // wb free + (kc==0) agg complete
            {   // stage 32x128 weight chunk to SMEM
                int kr = tid >> 4;
                const float4* g = (const float4*)(Wl + (kc * KC + kr) * HD + hbase);
                float4 v0 = g[0], v1 = g[1];
                *(float4*)(wb + kr * HD + hbase)     = v0;
                *(float4*)(wb + kr * HD + hbase + 4) = v1;
            }
            __syncthreads();
            const float* xrow0 = xs + (ty * 4) * XST + kc * KC;
            #pragma unroll 4
            for (int k = 0; k < KC; ++k) {
                const ulonglong2* wp = (const ulonglong2*)(wb + k * HD + hbase);
                ulonglong2 w01 = wp[0];
                ulonglong2 w23 = wp[1];
                #pragma unroll
                for (int i = 0; i < 4; ++i) {
                    float a = xrow0[i * XST + k];
                    unsigned long long a2 = pk2(a, a);
                    fma2(acc[i][0], a2, w01.x);
                    fma2(acc[i][1], a2, w01.y);
                    fma2(acc[i][2], a2, w23.x);
                    fma2(acc[i][3], a2, w23.y);
                }
            }
        }
        __syncthreads();
        // ELU + writeback to xs x-columns
        #pragma unroll
        for (int i = 0; i < 4; ++i) {
            int m = ty * 4 + i;
            if (m < MREAL) {
                float* dst = xs + m * XST + hbase;
                #pragma unroll
                for (int j = 0; j < 4; ++j) {
                    float lo, hi;
                    upk2(acc[i][j], lo, hi);
                    dst[2 * j]     = eluf(lo);
                    dst[2 * j + 1] = eluf(hi);
                }
            }
        }
        __syncthreads();
    }

    // ======== joint readout ========
    const int lane = tid & 31;
    const int wrp = tid >> 5;
    for (int t = wrp; t < SPC * NJ; t += NTHREADS / 32) {
        int s = t / NJ, j = t - s * NJ;
        const float* r0 = xs + (s * NN + c_jm0[j]) * XST;
        const float* r1 = xs + (s * NN + c_jm1[j]) * XST;
        const float* wj = Wout + j * 2 * HD;
        float sum = 0.0f;
        #pragma unroll
        for (int c = 0; c < 4; ++c) {
            int h = lane + 32 * c;
            sum += r0[h] * wj[h];
            sum += r1[h] * wj[HD + h];
        }
        #pragma unroll
        for (int o = 16; o; o >>= 1)
            sum += __shfl_xor_sync(0xffffffffu, sum, o);
        if (lane == 0)
            out[(size_t)(base_s + s) * NJ + j] = sum + bout[j];
    }
}

extern "C" void kernel_launch(void* const* d_in, const int* in_sizes, int n_in,
                              void* d_out, int out_size) {
    const float* obs  = (const float*)d_in[0];
    const float* W1   = (const float*)d_in[1];
    const float* b1   = (const float*)d_in[2];
    const float* W2   = (const float*)d_in[3];
    const float* b2   = (const float*)d_in[4];
    const float* Wmsg = (const float*)d_in[5];
    const float* bmsg = (const float*)d_in[6];
    const float* Wout = (const float*)d_in[7];
    const float* bout = (const float*)d_in[8];
    float* out = (float*)d_out;

    int B = in_sizes[0] / OBSD;
    int nblk = B / SPC;
    size_t smem = (size_t)(MROWS * XST + KC * HD + SPC * HD) * sizeof(float); // 152576 B

    cudaFuncSetAttribute(gnn_kernel, cudaFuncAttributeMaxDynamicSharedMemorySize, (int)smem);
    gnn_kernel<<<nblk, NTHREADS, smem>>>(obs, W1, b1, W2, b2, Wmsg, bmsg, Wout, bout, out);
}

// round 2
// speedup vs baseline: 1.0541x; 1.0541x over previous
#include <cuda_runtime.h>

#define NN 13
#define HD 128
#define NLAYER 8
#define NJ 17
#define DMAX 33
#define OBSD 348
#define SPC 8                 // samples per CTA
#define MREAL (SPC*NN)        // 104 real rows
#define MROWS 128             // padded M tile
#define XST 260               // xs row stride (floats), 16B-aligned rows
#define NTHREADS 512
#define KTOT 256
#define KC 64

// Feature gather indices (from _build_feature_indices), -1 = padded zero
__constant__ int c_feat[NN][DMAX] = {
  {0,1,2,3,4,22,23,24,25,26,27,45,46,47,48,49,50,51,52,53,54,175,176,177,178,179,180,270,271,272,273,274,275},
  {5,6,28,29,55,56,57,58,59,60,61,62,63,64,181,182,183,184,185,186,276,277,278,279,280,281,-1,-1,-1,-1,-1,-1,-1},
  {7,30,65,66,67,68,69,70,71,72,73,74,187,188,189,190,191,192,253,254,255,282,283,284,285,286,287,-1,-1,-1,-1,-1,-1},
  {8,9,10,11,31,32,33,34,75,76,77,78,79,80,81,82,83,84,193,194,195,196,197,198,256,257,258,288,289,290,291,292,293},
  {11,34,85,86,87,88,89,90,91,92,93,94,199,200,201,202,203,204,259,294,295,296,297,298,299,-1,-1,-1,-1,-1,-1,-1,-1},
  {95,96,97,98,99,100,101,102,103,104,205,206,207,208,209,210,300,301,302,303,304,305,-1,-1,-1,-1,-1,-1,-1,-1,-1,-1,-1},
  {12,13,14,15,35,36,37,38,105,106,107,108,109,110,111,112,113,114,211,212,213,214,215,216,260,261,262,306,307,308,309,310,311},
  {15,38,115,116,117,118,119,120,121,122,123,124,217,218,219,220,221,222,263,312,313,314,315,316,317,-1,-1,-1,-1,-1,-1,-1,-1},
  {125,126,127,128,129,130,131,132,133,134,223,224,225,226,227,228,318,319,320,321,322,323,-1,-1,-1,-1,-1,-1,-1,-1,-1,-1,-1},
  {16,17,18,39,40,41,135,136,137,138,139,140,141,142,143,144,229,230,231,232,233,234,264,265,324,325,326,327,328,329,-1,-1,-1},
  {18,41,145,146,147,148,149,150,151,152,153,154,235,236,237,238,239,240,266,330,331,332,333,334,335,-1,-1,-1,-1,-1,-1,-1,-1},
  {19,20,21,42,43,44,155,156,157,158,159,160,161,162,163,164,241,242,243,244,245,246,267,268,336,337,338,339,340,341,-1,-1,-1},
  {21,44,165,166,167,168,169,170,171,172,173,174,247,248,249,250,251,252,269,342,343,344,345,346,347,-1,-1,-1,-1,-1,-1,-1,-1}
};

// agg[n] = sum over neighbors (kinematic tree, both directions)
__constant__ int c_nbr[NN][3] = {
  {1,9,11},{0,2,0},{1,3,6},{2,4,0},{3,5,0},{4,0,0},{2,7,0},
  {6,8,0},{7,0,0},{0,10,0},{9,0,0},{0,12,0},{11,0,0}
};
__constant__ int c_deg[NN] = {3,2,3,2,2,1,2,2,1,2,1,2,1};

__constant__ int c_jm0[NJ] = {1,1,1,2,2,2,3,2,2,2,6,0,0,9,0,0,11};
__constant__ int c_jm1[NJ] = {2,2,2,3,3,3,4,6,6,6,7,9,9,10,11,11,12};

__device__ __forceinline__ float eluf(float x) {
    return x > 0.0f ? x : expm1f(x);
}
__device__ __forceinline__ unsigned long long pk2(float lo, float hi) {
    unsigned long long r;
    asm("mov.b64 %0, {%1, %2};" : "=l"(r) : "f"(lo), "f"(hi));
    return r;
}
__device__ __forceinline__ void upk2(unsigned long long v, float& lo, float& hi) {
    asm("mov.b64 {%0, %1}, %2;" : "=f"(lo), "=f"(hi) : "l"(v));
}
// Blackwell packed dual-FP32 FMA (FFMA2): 2x fp32 FMA throughput
__device__ __forceinline__ void fma2(unsigned long long& d, unsigned long long a, unsigned long long b) {
    asm("fma.rn.f32x2 %0, %1, %2, %0;" : "+l"(d) : "l"(a), "l"(b));
}

__global__ __launch_bounds__(NTHREADS, 1)
void gnn_kernel(const float* __restrict__ obs,
                const float* __restrict__ W1, const float* __restrict__ b1,
                const float* __restrict__ W2, const float* __restrict__ b2,
                const float* __restrict__ Wmsg, const float* __restrict__ bmsg,
                const float* __restrict__ Wout, const float* __restrict__ bout,
                float* __restrict__ out)
{
    extern __shared__ float sm[];
    float* xs = sm;                        // [MROWS][XST] : cols 0..127 = x, 128..255 = agg
    float* wb = sm + MROWS * XST;          // [KC][HD] weight chunk; doubles as obs buffer
    float* hb = wb + KC * HD;              // [SPC][HD] encoder hidden
    float* scratch = xs + MREAL * XST;     // pad rows (24*260 floats) as encoder reduce scratch

    const int tid = threadIdx.x;
    const int blk = blockIdx.x;
    const int base_s = blk * SPC;

    // ======== load obs tile ========
    float* obsb = wb; // [SPC][OBSD], 2784 floats <= 8192
    for (int i = tid; i < SPC * OBSD; i += NTHREADS) {
        int s = i / OBSD, f = i - s * OBSD;
        obsb[s * OBSD + f] = obs[(size_t)(base_s + s) * OBSD + f];
    }
    __syncthreads();

    const int hcol = tid & (HD - 1);
    const int sg = tid >> 7;   // 0..3 : K-split group

    // ======== encoder: x0 = W2 @ elu(W1 @ gather(obs)) per node ========
    for (int n = 0; n < NN; ++n) {
        // layer-1 partials, d-range split over sg, sample-paired FFMA2
        unsigned long long acc[4];
        #pragma unroll
        for (int p = 0; p < 4; ++p) acc[p] = 0ULL;
        for (int d = sg; d < DMAX; d += 4) {
            int fi = c_feat[n][d];
            if (fi >= 0) {
                float w = __ldg(&W1[(n * DMAX + d) * HD + hcol]);
                unsigned long long w2 = pk2(w, w);
                #pragma unroll
                for (int p = 0; p < 4; ++p) {
                    unsigned long long a2 = pk2(obsb[(2*p) * OBSD + fi],
                                                obsb[(2*p+1) * OBSD + fi]);
                    fma2(acc[p], a2, w2);
                }
            }
        }
        #pragma unroll
        for (int p = 0; p < 4; ++p) {
            float lo, hi;
            upk2(acc[p], lo, hi);
            scratch[(sg * SPC + 2*p    ) * HD + hcol] = lo;
            scratch[(sg * SPC + 2*p + 1) * HD + hcol] = hi;
        }
        __syncthreads();
        {   // reduce partials + bias + elu -> hb
            int s0 = sg * 2, s1 = s0 + 1;
            float v0 = b1[n * HD + hcol], v1 = v0;
            #pragma unroll
            for (int g = 0; g < 4; ++g) {
                v0 += scratch[(g * SPC + s0) * HD + hcol];
                v1 += scratch[(g * SPC + s1) * HD + hcol];
            }
            hb[s0 * HD + hcol] = eluf(v0);
            hb[s1 * HD + hcol] = eluf(v1);
        }
        __syncthreads();
        // layer-2 partials, k-range split over sg, sample-paired FFMA2
        unsigned long long acc2[4];
        #pragma unroll
        for (int p = 0; p < 4; ++p) acc2[p] = 0ULL;
        for (int kk = sg * 32; kk < sg * 32 + 32; ++kk) {
            float w = __ldg(&W2[(n * HD + kk) * HD + hcol]);
            unsigned long long w2 = pk2(w, w);
            #pragma unroll
            for (int p = 0; p < 4; ++p) {
                unsigned long long a2 = pk2(hb[(2*p) * HD + kk],
                                            hb[(2*p+1) * HD + kk]);
                fma2(acc2[p], a2, w2);
            }
        }
        #pragma unroll
        for (int p = 0; p < 4; ++p) {
            float lo, hi;
            upk2(acc2[p], lo, hi);
            scratch[(sg * SPC + 2*p    ) * HD + hcol] = lo;
            scratch[(sg * SPC + 2*p + 1) * HD + hcol] = hi;
        }
        __syncthreads();
        {   // reduce + bias -> xs (no activation, matches reference)
            int s0 = sg * 2, s1 = s0 + 1;
            float v0 = b2[n * HD + hcol], v1 = v0;
            #pragma unroll
            for (int g = 0; g < 4; ++g) {
                v0 += scratch[(g * SPC + s0) * HD + hcol];
                v1 += scratch[(g * SPC + s1) * HD + hcol];
            }
            xs[(s0 * NN + n) * XST + hcol] = v0;
            xs[(s1 * NN + n) * XST + hcol] = v1;
        }
        __syncthreads();
    }

    // zero the pad rows (they feed dummy GEMM threads, never written otherwise)
    for (int i = tid; i < (MROWS - MREAL) * XST; i += NTHREADS)
        xs[MREAL * XST + i] = 0.0f;

    const int tx = tid & 15;     // N block: cols [tx*8, tx*8+8)
    const int ty = tid >> 4;     // M block: rows [ty*4, ty*4+4)
    const int hbase = tx * 8;

    // ======== 8 message-passing layers ========
    for (int l = 0; l < NLAYER; ++l) {
        // aggregation (float4 over h): agg[s,n] = sum_{nb in N(n)} x[s,nb]
        for (int i = tid; i < MREAL * (HD/4); i += NTHREADS) {
            int h4 = i & 31;             // 32 float4 per row
            int m  = i >> 5;             // 0..103, m = s*13 + n
            int n = m % NN;
            int s13 = m - n;
            float4 sum = *(const float4*)(xs + (s13 + c_nbr[n][0]) * XST + h4*4);
            int dg = c_deg[n];
            #pragma unroll
            for (int e = 1; e < 3; ++e)
                if (e < dg) {
                    float4 v = *(const float4*)(xs + (s13 + c_nbr[n][e]) * XST + h4*4);
                    sum.x += v.x; sum.y += v.y; sum.z += v.z; sum.w += v.w;
                }
            *(float4*)(xs + m * XST + HD + h4*4) = sum;
        }

        // init packed accumulators with bias
        unsigned long long acc[4][4];
        {
            const float* bm = bmsg + l * HD + hbase;
            #pragma unroll
            for (int j = 0; j < 4; ++j) {
                unsigned long long bp = pk2(bm[2 * j], bm[2 * j + 1]);
                #pragma unroll
                for (int i = 0; i < 4; ++i) acc[i][j] = bp;
            }
        }

        const float* Wl = Wmsg + (size_t)l * KTOT * HD;
        for (int kc = 0; kc < KTOT / KC; ++kc) {
            __syncthreads();   // wb free + (kc==0) agg complete
            {   // stage 64x128 weight chunk to SMEM (8192 floats = 2048 float4)
                const float4* g = (const float4*)(Wl + kc * KC * HD);
                float4* w4 = (float4*)wb;
                #pragma unroll
                for (int r = 0; r < 4; ++r)
                    w4[tid + r * NTHREADS] = g[tid + r * NTHREADS];
            }
            __syncthreads();
            const float* xrow0 = xs + (ty * 4) * XST + kc * KC;
            #pragma unroll 2
            for (int k4 = 0; k4 < KC; k4 += 4) {
                float4 a0 = *(const float4*)(xrow0 + 0 * XST + k4);
                float4 a1 = *(const float4*)(xrow0 + 1 * XST + k4);
                float4 a2v = *(const float4*)(xrow0 + 2 * XST + k4);
                float4 a3 = *(const float4*)(xrow0 + 3 * XST + k4);
                #pragma unroll
                for (int kk = 0; kk < 4; ++kk) {
                    const ulonglong2* wp = (const ulonglong2*)(wb + (k4 + kk) * HD + hbase);
                    ulonglong2 w01 = wp[0];
                    ulonglong2 w23 = wp[1];
                    float e0 = (kk==0)?a0.x:(kk==1)?a0.y:(kk==2)?a0.z:a0.w;
                    float e1 = (kk==0)?a1.x:(kk==1)?a1.y:(kk==2)?a1.z:a1.w;
                    float e2 = (kk==0)?a2v.x:(kk==1)?a2v.y:(kk==2)?a2v.z:a2v.w;
                    float e3 = (kk==0)?a3.x:(kk==1)?a3.y:(kk==2)?a3.z:a3.w;
                    unsigned long long p0 = pk2(e0, e0);
                    unsigned long long p1 = pk2(e1, e1);
                    unsigned long long p2 = pk2(e2, e2);
                    unsigned long long p3 = pk2(e3, e3);
                    fma2(acc[0][0], p0, w01.x); fma2(acc[0][1], p0, w01.y);
                    fma2(acc[0][2], p0, w23.x); fma2(acc[0][3], p0, w23.y);
                    fma2(acc[1][0], p1, w01.x); fma2(acc[1][1], p1, w01.y);
                    fma2(acc[1][2], p1, w23.x); fma2(acc[1][3], p1, w23.y);
                    fma2(acc[2][0], p2, w01.x); fma2(acc[2][1], p2, w01.y);
                    fma2(acc[2][2], p2, w23.x); fma2(acc[2][3], p2, w23.y);
                    fma2(acc[3][0], p3, w01.x); fma2(acc[3][1], p3, w01.y);
                    fma2(acc[3][2], p3, w23.x); fma2(acc[3][3], p3, w23.y);
                }
            }
        }
        __syncthreads();
        // ELU + writeback to xs x-columns (float4 stores)
        #pragma unroll
        for (int i = 0; i < 4; ++i) {
            int m = ty * 4 + i;
            if (m < MREAL) {
                float* dst = xs + m * XST + hbase;
                float v[8];
                #pragma unroll
                for (int j = 0; j < 4; ++j) {
                    float lo, hi;
                    upk2(acc[i][j], lo, hi);
                    v[2*j]   = eluf(lo);
                    v[2*j+1] = eluf(hi);
                }
                *(float4*)(dst)     = make_float4(v[0], v[1], v[2], v[3]);
                *(float4*)(dst + 4) = make_float4(v[4], v[5], v[6], v[7]);
            }
        }
        __syncthreads();
    }

    // ======== joint readout ========
    const int lane = tid & 31;
    const int wrp = tid >> 5;
    for (int t = wrp; t < SPC * NJ; t += NTHREADS / 32) {
        int s = t / NJ, j = t - s * NJ;
        const float* r0 = xs + (s * NN + c_jm0[j]) * XST;
        const float* r1 = xs + (s * NN + c_jm1[j]) * XST;
        const float* wj = Wout + j * 2 * HD;
        float4 x0 = *(const float4*)(r0 + lane * 4);
        float4 x1 = *(const float4*)(r1 + lane * 4);
        float4 w0 = *(const float4*)(wj + lane * 4);
        float4 w1 = *(const float4*)(wj + HD + lane * 4);
        float sum = x0.x*w0.x + x0.y*w0.y + x0.z*w0.z + x0.w*w0.w
                  + x1.x*w1.x + x1.y*w1.y + x1.z*w1.z + x1.w*w1.w;
        #pragma unroll
        for (int o = 16; o; o >>= 1)
            sum += __shfl_xor_sync(0xffffffffu, sum, o);
        if (lane == 0)
            out[(size_t)(base_s + s) * NJ + j] = sum + bout[j];
    }
}

extern "C" void kernel_launch(void* const* d_in, const int* in_sizes, int n_in,
                              void* d_out, int out_size) {
    const float* obs  = (const float*)d_in[0];
    const float* W1   = (const float*)d_in[1];
    const float* b1   = (const float*)d_in[2];
    const float* W2   = (const float*)d_in[3];
    const float* b2   = (const float*)d_in[4];
    const float* Wmsg = (const float*)d_in[5];
    const float* bmsg = (const float*)d_in[6];
    const float* Wout = (const float*)d_in[7];
    const float* bout = (const float*)d_in[8];
    float* out = (float*)d_out;

    int B = in_sizes[0] / OBSD;
    int nblk = B / SPC;
    size_t smem = (size_t)(MROWS * XST + KC * HD + SPC * HD) * sizeof(float); // 169984 B

    cudaFuncSetAttribute(gnn_kernel, cudaFuncAttributeMaxDynamicSharedMemorySize, (int)smem);
    gnn_kernel<<<nblk, NTHREADS, smem>>>(obs, W1, b1, W2, b2, Wmsg, bmsg, Wout, bout, out);
}

// round 3
// speedup vs baseline: 1.5690x; 1.4884x over previous
#include <cuda_runtime.h>

#define NN 13
#define HD 128
#define NLAYER 8
#define NJ 17
#define DMAX 33
#define OBSD 348
#define SPC 8                 // samples per CTA
#define MREAL (SPC*NN)        // 104 rows
#define XST 260               // xs row stride (floats), 16B-aligned rows
#define NTHREADS 256
#define KTOT 256
#define KC 64

__constant__ int c_feat[NN][DMAX] = {
  {0,1,2,3,4,22,23,24,25,26,27,45,46,47,48,49,50,51,52,53,54,175,176,177,178,179,180,270,271,272,273,274,275},
  {5,6,28,29,55,56,57,58,59,60,61,62,63,64,181,182,183,184,185,186,276,277,278,279,280,281,0,0,0,0,0,0,0},
  {7,30,65,66,67,68,69,70,71,72,73,74,187,188,189,190,191,192,253,254,255,282,283,284,285,286,287,0,0,0,0,0,0},
  {8,9,10,11,31,32,33,34,75,76,77,78,79,80,81,82,83,84,193,194,195,196,197,198,256,257,258,288,289,290,291,292,293},
  {11,34,85,86,87,88,89,90,91,92,93,94,199,200,201,202,203,204,259,294,295,296,297,298,299,0,0,0,0,0,0,0,0},
  {95,96,97,98,99,100,101,102,103,104,205,206,207,208,209,210,300,301,302,303,304,305,0,0,0,0,0,0,0,0,0,0,0},
  {12,13,14,15,35,36,37,38,105,106,107,108,109,110,111,112,113,114,211,212,213,214,215,216,260,261,262,306,307,308,309,310,311},
  {15,38,115,116,117,118,119,120,121,122,123,124,217,218,219,220,221,222,263,312,313,314,315,316,317,0,0,0,0,0,0,0,0},
  {125,126,127,128,129,130,131,132,133,134,223,224,225,226,227,228,318,319,320,321,322,323,0,0,0,0,0,0,0,0,0,0,0},
  {16,17,18,39,40,41,135,136,137,138,139,140,141,142,143,144,229,230,231,232,233,234,264,265,324,325,326,327,328,329,0,0,0},
  {18,41,145,146,147,148,149,150,151,152,153,154,235,236,237,238,239,240,266,330,331,332,333,334,335,0,0,0,0,0,0,0,0},
  {19,20,21,42,43,44,155,156,157,158,159,160,161,162,163,164,241,242,243,244,245,246,267,268,336,337,338,339,340,341,0,0,0},
  {21,44,165,166,167,168,169,170,171,172,173,174,247,248,249,250,251,252,269,342,343,344,345,346,347,0,0,0,0,0,0,0,0}
};
__constant__ int c_dcnt[NN] = {33,26,27,33,25,22,33,25,22,30,25,30,25};

__constant__ int c_nbr[NN][3] = {
  {1,9,11},{0,2,0},{1,3,6},{2,4,0},{3,5,0},{4,0,0},{2,7,0},
  {6,8,0},{7,0,0},{0,10,0},{9,0,0},{0,12,0},{11,0,0}
};
__constant__ int c_deg[NN] = {3,2,3,2,2,1,2,2,1,2,1,2,1};

__constant__ int c_jm0[NJ] = {1,1,1,2,2,2,3,2,2,2,6,0,0,9,0,0,11};
__constant__ int c_jm1[NJ] = {2,2,2,3,3,3,4,6,6,6,7,9,9,10,11,11,12};

__device__ __forceinline__ float eluf(float x) {
    return x > 0.0f ? x : expm1f(x);
}
__device__ __forceinline__ unsigned long long pk2(float lo, float hi) {
    unsigned long long r;
    asm("mov.b64 %0, {%1, %2};" : "=l"(r) : "f"(lo), "f"(hi));
    return r;
}
__device__ __forceinline__ void upk2(unsigned long long v, float& lo, float& hi) {
    asm("mov.b64 {%0, %1}, %2;" : "=f"(lo), "=f"(hi) : "l"(v));
}
// Blackwell packed dual-FP32 FMA: 2x fp32 throughput, exact IEEE fp32 lanes
__device__ __forceinline__ void fma2(unsigned long long& d, unsigned long long a, unsigned long long b) {
    asm("fma.rn.f32x2 %0, %1, %2, %0;" : "+l"(d) : "l"(a), "l"(b));
}

__global__ __launch_bounds__(NTHREADS, 1)
void gnn_kernel(const float* __restrict__ obs,
                const float* __restrict__ W1, const float* __restrict__ b1,
                const float* __restrict__ W2, const float* __restrict__ b2,
                const float* __restrict__ Wmsg, const float* __restrict__ bmsg,
                const float* __restrict__ Wout, const float* __restrict__ bout,
                float* __restrict__ out)
{
    extern __shared__ float sm[];
    float* xs = sm;                        // [MREAL][XST]: cols 0..127 = x, 128..255 = agg/h
    float* wb = sm + MREAL * XST;          // [KC][HD] weight chunk; doubles as obs buffer

    const int tid = threadIdx.x;
    const int base_s = blockIdx.x * SPC;

    const int tx = tid & 15;               // column-pair group: pairs {tx+16j}, j=0..3
    const int ty = tid >> 4;               // 0..15

    // ======== load obs tile ========
    float* obsb = wb; // [SPC][OBSD] = 2784 floats <= 8192
    {
        const float4* g = (const float4*)(obs + (size_t)base_s * OBSD);
        float4* o4 = (float4*)obsb;
        for (int i = tid; i < SPC * OBSD / 4; i += NTHREADS) o4[i] = g[i];
    }
    __syncthreads();

    // ======== encoder phase 1: h = elu(gather(obs) @ W1[n] + b1[n]) -> xs agg cols ========
    if (ty < NN) {
        const int n = ty;
        unsigned long long acc[SPC][4];
        {
            const unsigned long long* bp = (const unsigned long long*)(b1 + n * HD);
            #pragma unroll
            for (int j = 0; j < 4; ++j) {
                unsigned long long bj = bp[tx + 16 * j];
                #pragma unroll
                for (int s = 0; s < SPC; ++s) acc[s][j] = bj;
            }
        }
        const int dc = c_dcnt[n];
        #pragma unroll 1
        for (int d = 0; d < dc; ++d) {
            const int fi = c_feat[n][d];
            const unsigned long long* wr =
                (const unsigned long long*)(W1 + (n * DMAX + d) * HD);
            unsigned long long w0 = wr[tx], w1 = wr[tx+16], w2 = wr[tx+32], w3 = wr[tx+48];
            #pragma unroll
            for (int s = 0; s < SPC; ++s) {
                float xe = obsb[s * OBSD + fi];
                unsigned long long p = pk2(xe, xe);
                fma2(acc[s][0], p, w0); fma2(acc[s][1], p, w1);
                fma2(acc[s][2], p, w2); fma2(acc[s][3], p, w3);
            }
        }
        #pragma unroll
        for (int s = 0; s < SPC; ++s) {
            float* dst = xs + (s * NN + n) * XST + HD;
            #pragma unroll
            for (int j = 0; j < 4; ++j) {
                float lo, hi; upk2(acc[s][j], lo, hi);
                *(float2*)(dst + 2 * (tx + 16 * j)) = make_float2(eluf(lo), eluf(hi));
            }
        }
    }
    __syncthreads();

    // ======== encoder phase 2: x0 = h @ W2[n] + b2[n] -> xs x cols ========
    if (ty < NN) {
        const int n = ty;
        unsigned long long acc[SPC][4];
        {
            const unsigned long long* bp = (const unsigned long long*)(b2 + n * HD);
            #pragma unroll
            for (int j = 0; j < 4; ++j) {
                unsigned long long bj = bp[tx + 16 * j];
                #pragma unroll
                for (int s = 0; s < SPC; ++s) acc[s][j] = bj;
            }
        }
        #pragma unroll 2
        for (int k = 0; k < HD; ++k) {
            const unsigned long long* wr =
                (const unsigned long long*)(W2 + (n * HD + k) * HD);
            unsigned long long w0 = wr[tx], w1 = wr[tx+16], w2 = wr[tx+32], w3 = wr[tx+48];
            #pragma unroll
            for (int s = 0; s < SPC; ++s) {
                float xe = xs[(s * NN + n) * XST + HD + k];
                unsigned long long p = pk2(xe, xe);
                fma2(acc[s][0], p, w0); fma2(acc[s][1], p, w1);
                fma2(acc[s][2], p, w2); fma2(acc[s][3], p, w3);
            }
        }
        #pragma unroll
        for (int s = 0; s < SPC; ++s) {
            float* dst = xs + (s * NN + n) * XST;
            #pragma unroll
            for (int j = 0; j < 4; ++j) {
                float lo, hi; upk2(acc[s][j], lo, hi);
                *(float2*)(dst + 2 * (tx + 16 * j)) = make_float2(lo, hi);
            }
        }
    }
    __syncthreads();

    // SMSP-balanced row tiling: ty<8 -> 7 rows, ty>=8 -> 6 rows (total 104)
    const int R = (ty < 8) ? 7 : 6;
    const int row0 = (ty < 8) ? ty * 7 : 56 + (ty - 8) * 6;
    int roff[7];
    #pragma unroll
    for (int r = 0; r < 7; ++r) roff[r] = (row0 + ((r < R) ? r : R - 1)) * XST;

    // ======== 8 message-passing layers ========
    for (int l = 0; l < NLAYER; ++l) {
        // aggregation: agg[s,n] = sum_{nb} x[s,nb]  (float4 over h)
        for (int i = tid; i < MREAL * (HD / 4); i += NTHREADS) {
            int h4 = i & 31;
            int m  = i >> 5;
            int n = m % NN;
            int s13 = m - n;
            float4 sum = *(const float4*)(xs + (s13 + c_nbr[n][0]) * XST + h4 * 4);
            int dg = c_deg[n];
            #pragma unroll
            for (int e = 1; e < 3; ++e)
                if (e < dg) {
                    float4 v = *(const float4*)(xs + (s13 + c_nbr[n][e]) * XST + h4 * 4);
                    sum.x += v.x; sum.y += v.y; sum.z += v.z; sum.w += v.w;
                }
            *(float4*)(xs + m * XST + HD + h4 * 4) = sum;
        }

        unsigned long long acc[7][4];
        {
            const unsigned long long* bp = (const unsigned long long*)(bmsg + l * HD);
            #pragma unroll
            for (int j = 0; j < 4; ++j) {
                unsigned long long bj = bp[tx + 16 * j];
                #pragma unroll
                for (int r = 0; r < 7; ++r) acc[r][j] = bj;
            }
        }

        const float* Wl = Wmsg + (size_t)l * KTOT * HD;
        for (int kc = 0; kc < KTOT / KC; ++kc) {
            __syncthreads();   // wb free + (kc==0) agg complete
            {   // stage 64x128 weight chunk (2048 float4)
                const float4* g = (const float4*)(Wl + kc * KC * HD);
                float4* w4 = (float4*)wb;
                #pragma unroll
                for (int r = 0; r < 8; ++r)
                    w4[tid + r * NTHREADS] = g[tid + r * NTHREADS];
            }
            __syncthreads();
            const float* xk = xs + kc * KC;
            #pragma unroll 1
            for (int k4 = 0; k4 < KC; k4 += 4) {
                float4 a[7];
                #pragma unroll
                for (int r = 0; r < 7; ++r)
                    a[r] = *(const float4*)(xk + roff[r] + k4);
                #pragma unroll
                for (int kk = 0; kk < 4; ++kk) {
                    const unsigned long long* wr =
                        (const unsigned long long*)(wb + (k4 + kk) * HD);
                    unsigned long long w0 = wr[tx], w1 = wr[tx+16],
                                       w2 = wr[tx+32], w3 = wr[tx+48];
                    #pragma unroll
                    for (int r = 0; r < 7; ++r) {
                        const float* af = (const float*)&a[r];
                        float xe = af[kk];
                        unsigned long long p = pk2(xe, xe);
                        fma2(acc[r][0], p, w0); fma2(acc[r][1], p, w1);
                        fma2(acc[r][2], p, w2); fma2(acc[r][3], p, w3);
                    }
                }
            }
        }
        __syncthreads();
        // ELU + writeback
        #pragma unroll
        for (int r = 0; r < 7; ++r) {
            if (r < R) {
                float* dst = xs + (row0 + r) * XST;
                #pragma unroll
                for (int j = 0; j < 4; ++j) {
                    float lo, hi; upk2(acc[r][j], lo, hi);
                    *(float2*)(dst + 2 * (tx + 16 * j)) = make_float2(eluf(lo), eluf(hi));
                }
            }
        }
        __syncthreads();
    }

    // ======== joint readout ========
    const int lane = tid & 31;
    const int wrp = tid >> 5;
    for (int t = wrp; t < SPC * NJ; t += NTHREADS / 32) {
        int s = t / NJ, j = t - s * NJ;
        const float* r0 = xs + (s * NN + c_jm0[j]) * XST;
        const float* r1 = xs + (s * NN + c_jm1[j]) * XST;
        const float* wj = Wout + j * 2 * HD;
        float4 x0 = *(const float4*)(r0 + lane * 4);
        float4 x1 = *(const float4*)(r1 + lane * 4);
        float4 w0 = *(const float4*)(wj + lane * 4);
        float4 w1 = *(const float4*)(wj + HD + lane * 4);
        float sum = x0.x*w0.x + x0.y*w0.y + x0.z*w0.z + x0.w*w0.w
                  + x1.x*w1.x + x1.y*w1.y + x1.z*w1.z + x1.w*w1.w;
        #pragma unroll
        for (int o = 16; o; o >>= 1)
            sum += __shfl_xor_sync(0xffffffffu, sum, o);
        if (lane == 0)
            out[(size_t)(base_s + s) * NJ + j] = sum + bout[j];
    }
}

extern "C" void kernel_launch(void* const* d_in, const int* in_sizes, int n_in,
                              void* d_out, int out_size) {
    const float* obs  = (const float*)d_in[0];
    const float* W1   = (const float*)d_in[1];
    const float* b1   = (const float*)d_in[2];
    const float* W2   = (const float*)d_in[3];
    const float* b2   = (const float*)d_in[4];
    const float* Wmsg = (const float*)d_in[5];
    const float* bmsg = (const float*)d_in[6];
    const float* Wout = (const float*)d_in[7];
    const float* bout = (const float*)d_in[8];
    float* out = (float*)d_out;

    int B = in_sizes[0] / OBSD;
    int nblk = B / SPC;
    size_t smem = (size_t)(MREAL * XST + KC * HD) * sizeof(float); // 140928 B

    cudaFuncSetAttribute(gnn_kernel, cudaFuncAttributeMaxDynamicSharedMemorySize, (int)smem);
    gnn_kernel<<<nblk, NTHREADS, smem>>>(obs, W1, b1, W2, b2, Wmsg, bmsg, Wout, bout, out);
}

// round 4
// speedup vs baseline: 1.7358x; 1.1063x over previous
#include <cuda_runtime.h>

#define NN 13
#define HD 128
#define NLAYER 8
#define NJ 17
#define DMAX 33
#define OBSD 348
#define SPC 8                 // samples per CTA
#define MREAL (SPC*NN)        // 104 rows
#define XST 260               // xs row stride (floats), 16B-aligned rows
#define NTHREADS 512
#define KTOT 256
#define KC 64

__constant__ int c_feat[NN][DMAX] = {
  {0,1,2,3,4,22,23,24,25,26,27,45,46,47,48,49,50,51,52,53,54,175,176,177,178,179,180,270,271,272,273,274,275},
  {5,6,28,29,55,56,57,58,59,60,61,62,63,64,181,182,183,184,185,186,276,277,278,279,280,281,0,0,0,0,0,0,0},
  {7,30,65,66,67,68,69,70,71,72,73,74,187,188,189,190,191,192,253,254,255,282,283,284,285,286,287,0,0,0,0,0,0},
  {8,9,10,11,31,32,33,34,75,76,77,78,79,80,81,82,83,84,193,194,195,196,197,198,256,257,258,288,289,290,291,292,293},
  {11,34,85,86,87,88,89,90,91,92,93,94,199,200,201,202,203,204,259,294,295,296,297,298,299,0,0,0,0,0,0,0,0},
  {95,96,97,98,99,100,101,102,103,104,205,206,207,208,209,210,300,301,302,303,304,305,0,0,0,0,0,0,0,0,0,0,0},
  {12,13,14,15,35,36,37,38,105,106,107,108,109,110,111,112,113,114,211,212,213,214,215,216,260,261,262,306,307,308,309,310,311},
  {15,38,115,116,117,118,119,120,121,122,123,124,217,218,219,220,221,222,263,312,313,314,315,316,317,0,0,0,0,0,0,0,0},
  {125,126,127,128,129,130,131,132,133,134,223,224,225,226,227,228,318,319,320,321,322,323,0,0,0,0,0,0,0,0,0,0,0},
  {16,17,18,39,40,41,135,136,137,138,139,140,141,142,143,144,229,230,231,232,233,234,264,265,324,325,326,327,328,329,0,0,0},
  {18,41,145,146,147,148,149,150,151,152,153,154,235,236,237,238,239,240,266,330,331,332,333,334,335,0,0,0,0,0,0,0,0},
  {19,20,21,42,43,44,155,156,157,158,159,160,161,162,163,164,241,242,243,244,245,246,267,268,336,337,338,339,340,341,0,0,0},
  {21,44,165,166,167,168,169,170,171,172,173,174,247,248,249,250,251,252,269,342,343,344,345,346,347,0,0,0,0,0,0,0,0}
};
__constant__ int c_dcnt[NN] = {33,26,27,33,25,22,33,25,22,30,25,30,25};

__constant__ int c_nbr[NN][3] = {
  {1,9,11},{0,2,0},{1,3,6},{2,4,0},{3,5,0},{4,0,0},{2,7,0},
  {6,8,0},{7,0,0},{0,10,0},{9,0,0},{0,12,0},{11,0,0}
};
__constant__ int c_deg[NN] = {3,2,3,2,2,1,2,2,1,2,1,2,1};

__constant__ int c_jm0[NJ] = {1,1,1,2,2,2,3,2,2,2,6,0,0,9,0,0,11};
__constant__ int c_jm1[NJ] = {2,2,2,3,3,3,4,6,6,6,7,9,9,10,11,11,12};

__device__ __forceinline__ float eluf(float x) {
    return x > 0.0f ? x : expm1f(x);
}
__device__ __forceinline__ unsigned long long pk2(float lo, float hi) {
    unsigned long long r;
    asm("mov.b64 %0, {%1, %2};" : "=l"(r) : "f"(lo), "f"(hi));
    return r;
}
__device__ __forceinline__ void upk2(unsigned long long v, float& lo, float& hi) {
    asm("mov.b64 {%0, %1}, %2;" : "=f"(lo), "=f"(hi) : "l"(v));
}
// Blackwell packed dual-FP32 FMA: 2x fp32 throughput, exact IEEE fp32 lanes
__device__ __forceinline__ void fma2(unsigned long long& d, unsigned long long a, unsigned long long b) {
    asm("fma.rn.f32x2 %0, %1, %2, %0;" : "+l"(d) : "l"(a), "l"(b));
}

__global__ __launch_bounds__(NTHREADS, 1)
void gnn_kernel(const float* __restrict__ obs,
                const float* __restrict__ W1, const float* __restrict__ b1,
                const float* __restrict__ W2, const float* __restrict__ b2,
                const float* __restrict__ Wmsg, const float* __restrict__ bmsg,
                const float* __restrict__ Wout, const float* __restrict__ bout,
                float* __restrict__ out)
{
    extern __shared__ float sm[];
    float* xs = sm;                        // [MREAL][XST]: cols 0..127 = x, 128..255 = agg/h
    float* wb = sm + MREAL * XST;          // 2 x [KC][HD] weight ping-pong; doubles as obs buffer

    const int tid = threadIdx.x;
    const int base_s = blockIdx.x * SPC;

    const int tx = tid & 31;               // ull column pair: cols {tx, tx+32} (of 64)
    const int ty = tid >> 5;               // 0..15 row group

    // ======== load obs tile ========
    float* obsb = wb; // [SPC][OBSD] = 2784 floats
    {
        const float4* g = (const float4*)(obs + (size_t)base_s * OBSD);
        float4* o4 = (float4*)obsb;
        for (int i = tid; i < SPC * OBSD / 4; i += NTHREADS) o4[i] = g[i];
    }
    __syncthreads();

    // ======== encoder phase 1: h = elu(gather(obs) @ W1[n] + b1[n]) -> xs agg cols ========
    if (ty < NN) {
        const int n = ty;
        unsigned long long acc[SPC][2];
        {
            const unsigned long long* bp = (const unsigned long long*)(b1 + n * HD);
            unsigned long long b0 = bp[tx], b1v = bp[tx + 32];
            #pragma unroll
            for (int s = 0; s < SPC; ++s) { acc[s][0] = b0; acc[s][1] = b1v; }
        }
        const int dc = c_dcnt[n];
        #pragma unroll 1
        for (int d = 0; d < dc; ++d) {
            const int fi = c_feat[n][d];
            const unsigned long long* wr =
                (const unsigned long long*)(W1 + (n * DMAX + d) * HD);
            unsigned long long w0 = wr[tx], w1 = wr[tx + 32];
            #pragma unroll
            for (int s = 0; s < SPC; ++s) {
                float xe = obsb[s * OBSD + fi];
                unsigned long long p = pk2(xe, xe);
                fma2(acc[s][0], p, w0); fma2(acc[s][1], p, w1);
            }
        }
        #pragma unroll
        for (int s = 0; s < SPC; ++s) {
            float* dst = xs + (s * NN + n) * XST + HD;
            float lo, hi;
            upk2(acc[s][0], lo, hi);
            *(float2*)(dst + 2 * tx) = make_float2(eluf(lo), eluf(hi));
            upk2(acc[s][1], lo, hi);
            *(float2*)(dst + 2 * tx + 64) = make_float2(eluf(lo), eluf(hi));
        }
    }
    __syncthreads();

    // ======== encoder phase 2: x0 = h @ W2[n] + b2[n] -> xs x cols ========
    if (ty < NN) {
        const int n = ty;
        unsigned long long acc[SPC][2];
        {
            const unsigned long long* bp = (const unsigned long long*)(b2 + n * HD);
            unsigned long long b0 = bp[tx], b1v = bp[tx + 32];
            #pragma unroll
            for (int s = 0; s < SPC; ++s) { acc[s][0] = b0; acc[s][1] = b1v; }
        }
        #pragma unroll 2
        for (int k = 0; k < HD; ++k) {
            const unsigned long long* wr =
                (const unsigned long long*)(W2 + (n * HD + k) * HD);
            unsigned long long w0 = wr[tx], w1 = wr[tx + 32];
            #pragma unroll
            for (int s = 0; s < SPC; ++s) {
                float xe = xs[(s * NN + n) * XST + HD + k];
                unsigned long long p = pk2(xe, xe);
                fma2(acc[s][0], p, w0); fma2(acc[s][1], p, w1);
            }
        }
        #pragma unroll
        for (int s = 0; s < SPC; ++s) {
            float* dst = xs + (s * NN + n) * XST;
            float lo, hi;
            upk2(acc[s][0], lo, hi);
            *(float2*)(dst + 2 * tx) = make_float2(lo, hi);
            upk2(acc[s][1], lo, hi);
            *(float2*)(dst + 2 * tx + 64) = make_float2(lo, hi);
        }
    }

    // SMSP-balanced row tiling: ty<8 -> 7 rows, ty>=8 -> 6 rows (total 104)
    const int R = (ty < 8) ? 7 : 6;
    const int row0 = (ty < 8) ? ty * 7 : 56 + (ty - 8) * 6;
    int roff[7];
    #pragma unroll
    for (int r = 0; r < 7; ++r) roff[r] = (row0 + ((r < R) ? r : R - 1)) * XST;

    // ======== 8 message-passing layers ========
    for (int l = 0; l < NLAYER; ++l) {
        const float* Wl = Wmsg + (size_t)l * KTOT * HD;

        // prefetch weight chunk 0 into registers (overlaps with aggregation)
        float4 wreg[4];
        {
            const float4* g = (const float4*)Wl;
            #pragma unroll
            for (int r = 0; r < 4; ++r) wreg[r] = g[tid + r * NTHREADS];
        }

        __syncthreads();   // encoder / previous writeback complete
        // aggregation: agg[s,n] = sum_{nb} x[s,nb]  (float4 over h)
        for (int i = tid; i < MREAL * (HD / 4); i += NTHREADS) {
            int h4 = i & 31;
            int m  = i >> 5;
            int n = m % NN;
            int s13 = m - n;
            float4 sum = *(const float4*)(xs + (s13 + c_nbr[n][0]) * XST + h4 * 4);
            int dg = c_deg[n];
            #pragma unroll
            for (int e = 1; e < 3; ++e)
                if (e < dg) {
                    float4 v = *(const float4*)(xs + (s13 + c_nbr[n][e]) * XST + h4 * 4);
                    sum.x += v.x; sum.y += v.y; sum.z += v.z; sum.w += v.w;
                }
            *(float4*)(xs + m * XST + HD + h4 * 4) = sum;
        }
        // store chunk 0 to ping buffer
        {
            float4* d4 = (float4*)wb;
            #pragma unroll
            for (int r = 0; r < 4; ++r) d4[tid + r * NTHREADS] = wreg[r];
        }

        unsigned long long acc[7][2];
        {
            const unsigned long long* bp = (const unsigned long long*)(bmsg + l * HD);
            unsigned long long b0 = bp[tx], b1v = bp[tx + 32];
            #pragma unroll
            for (int r = 0; r < 7; ++r) { acc[r][0] = b0; acc[r][1] = b1v; }
        }

        for (int kc = 0; kc < KTOT / KC; ++kc) {
            __syncthreads();   // current buffer staged; prior reads of next buffer done
            if (kc < KTOT / KC - 1) {   // prefetch next chunk into registers
                const float4* g = (const float4*)(Wl + (kc + 1) * KC * HD);
                #pragma unroll
                for (int r = 0; r < 4; ++r) wreg[r] = g[tid + r * NTHREADS];
            }
            const float* cur = wb + (kc & 1) * (KC * HD);
            const float* xk = xs + kc * KC;
            #pragma unroll 1
            for (int k4 = 0; k4 < KC; k4 += 4) {
                float4 a[7];
                #pragma unroll
                for (int r = 0; r < 7; ++r)
                    a[r] = *(const float4*)(xk + roff[r] + k4);
                #pragma unroll
                for (int kk = 0; kk < 4; ++kk) {
                    const unsigned long long* wr =
                        (const unsigned long long*)(cur + (k4 + kk) * HD);
                    unsigned long long w0 = wr[tx], w1 = wr[tx + 32];
                    #pragma unroll
                    for (int r = 0; r < 7; ++r) {
                        const float* af = (const float*)&a[r];
                        float xe = af[kk];
                        unsigned long long p = pk2(xe, xe);
                        fma2(acc[r][0], p, w0);
                        fma2(acc[r][1], p, w1);
                    }
                }
            }
            if (kc < KTOT / KC - 1) {   // store next chunk to pong buffer
                float4* d4 = (float4*)(wb + ((kc + 1) & 1) * (KC * HD));
                #pragma unroll
                for (int r = 0; r < 4; ++r) d4[tid + r * NTHREADS] = wreg[r];
            }
        }
        __syncthreads();
        // ELU + writeback
        #pragma unroll
        for (int r = 0; r < 7; ++r) {
            if (r < R) {
                float* dst = xs + (row0 + r) * XST;
                float lo, hi;
                upk2(acc[r][0], lo, hi);
                *(float2*)(dst + 2 * tx) = make_float2(eluf(lo), eluf(hi));
                upk2(acc[r][1], lo, hi);
                *(float2*)(dst + 2 * tx + 64) = make_float2(eluf(lo), eluf(hi));
            }
        }
    }
    __syncthreads();

    // ======== joint readout ========
    const int lane = tid & 31;
    const int wrp = tid >> 5;
    for (int t = wrp; t < SPC * NJ; t += NTHREADS / 32) {
        int s = t / NJ, j = t - s * NJ;
        const float* r0 = xs + (s * NN + c_jm0[j]) * XST;
        const float* r1 = xs + (s * NN + c_jm1[j]) * XST;
        const float* wj = Wout + j * 2 * HD;
        float4 x0 = *(const float4*)(r0 + lane * 4);
        float4 x1 = *(const float4*)(r1 + lane * 4);
        float4 w0 = *(const float4*)(wj + lane * 4);
        float4 w1 = *(const float4*)(wj + HD + lane * 4);
        float sum = x0.x*w0.x + x0.y*w0.y + x0.z*w0.z + x0.w*w0.w
                  + x1.x*w1.x + x1.y*w1.y + x1.z*w1.z + x1.w*w1.w;
        #pragma unroll
        for (int o = 16; o; o >>= 1)
            sum += __shfl_xor_sync(0xffffffffu, sum, o);
        if (lane == 0)
            out[(size_t)(base_s + s) * NJ + j] = sum + bout[j];
    }
}

extern "C" void kernel_launch(void* const* d_in, const int* in_sizes, int n_in,
                              void* d_out, int out_size) {
    const float* obs  = (const float*)d_in[0];
    const float* W1   = (const float*)d_in[1];
    const float* b1   = (const float*)d_in[2];
    const float* W2   = (const float*)d_in[3];
    const float* b2   = (const float*)d_in[4];
    const float* Wmsg = (const float*)d_in[5];
    const float* bmsg = (const float*)d_in[6];
    const float* Wout = (const float*)d_in[7];
    const float* bout = (const float*)d_in[8];
    float* out = (float*)d_out;

    int B = in_sizes[0] / OBSD;
    int nblk = B / SPC;
    size_t smem = (size_t)(MREAL * XST + 2 * KC * HD) * sizeof(float); // 173696 B

    cudaFuncSetAttribute(gnn_kernel, cudaFuncAttributeMaxDynamicSharedMemorySize, (int)smem);
    gnn_kernel<<<nblk, NTHREADS, smem>>>(obs, W1, b1, W2, b2, Wmsg, bmsg, Wout, bout, out);
}